// round 1
// baseline (speedup 1.0000x reference)
#include <cuda_runtime.h>
#include <cuda_bf16.h>
#include <mma.h>
#include <math.h>

using namespace nvcuda;

// Problem constants
#define BB 4
#define LL 2048
#define DD 512
#define HH 8
#define QDIM 64
#define FFD 2048
#define MTOT (BB*LL)          // 8192
#define EPS 1e-5f
#define ATT_SCALE 0.125f      // 1/sqrt(64)

// -------------------- scratch (device globals; no allocation allowed) -----
__device__ float g_q  [MTOT*DD];
__device__ float g_k  [MTOT*DD];
__device__ float g_v  [MTOT*DD];
__device__ float g_att[MTOT*DD];
__device__ float g_t1 [MTOT*DD];   // z @ WZ
__device__ float g_zn [MTOT*DD];   // post-LN1 residual branch
__device__ float g_h  [MTOT*FFD];  // FF hidden
__device__ float g_o2 [MTOT*DD];   // FF out

// ===========================================================================
// Tiled tf32 GEMM: C[M,N] = A[M,K] @ B[K,N]   (row-major, all dims %128/%32)
// Block tile 128x128, BK=32, 256 threads (8 warps), warp tile 64x32.
// ===========================================================================
__global__ __launch_bounds__(256) void gemm_tf32_kernel(
    const float* __restrict__ A, const float* __restrict__ B,
    float* __restrict__ C, int M, int N, int K)
{
    __shared__ float As[128*36];   // ld 36
    __shared__ float Bs[32*132];   // ld 132

    const int tid = threadIdx.x;
    const int w   = tid >> 5;
    const int wm  = w >> 2;        // 0..1
    const int wn  = w & 3;         // 0..3
    const int mBase = blockIdx.y * 128;
    const int nBase = blockIdx.x * 128;

    wmma::fragment<wmma::accumulator, 16,16,8, float> acc[4][2];
    #pragma unroll
    for (int mi=0; mi<4; mi++)
      #pragma unroll
      for (int ni=0; ni<2; ni++) wmma::fill_fragment(acc[mi][ni], 0.0f);

    for (int k0 = 0; k0 < K; k0 += 32) {
        // load A 128x32
        #pragma unroll
        for (int i=0;i<4;i++) {
            int f = tid + i*256;
            int r = f >> 3, c4 = f & 7;
            float4 val = *(const float4*)&A[(size_t)(mBase + r)*K + k0 + c4*4];
            *(float4*)&As[r*36 + c4*4] = val;
        }
        // load B 32x128
        #pragma unroll
        for (int i=0;i<4;i++) {
            int f = tid + i*256;
            int r = f >> 5, c4 = f & 31;
            float4 val = *(const float4*)&B[(size_t)(k0 + r)*N + nBase + c4*4];
            *(float4*)&Bs[r*132 + c4*4] = val;
        }
        __syncthreads();

        #pragma unroll
        for (int kk=0; kk<4; kk++) {
            wmma::fragment<wmma::matrix_a, 16,16,8, wmma::precision::tf32, wmma::row_major> af[4];
            wmma::fragment<wmma::matrix_b, 16,16,8, wmma::precision::tf32, wmma::row_major> bf[2];
            #pragma unroll
            for (int mi=0; mi<4; mi++) {
                wmma::load_matrix_sync(af[mi], &As[(wm*64 + mi*16)*36 + kk*8], 36);
                #pragma unroll
                for (int t=0; t<af[mi].num_elements; t++)
                    af[mi].x[t] = wmma::__float_to_tf32(af[mi].x[t]);
            }
            #pragma unroll
            for (int ni=0; ni<2; ni++) {
                wmma::load_matrix_sync(bf[ni], &Bs[(kk*8)*132 + wn*32 + ni*16], 132);
                #pragma unroll
                for (int t=0; t<bf[ni].num_elements; t++)
                    bf[ni].x[t] = wmma::__float_to_tf32(bf[ni].x[t]);
            }
            #pragma unroll
            for (int mi=0; mi<4; mi++)
              #pragma unroll
              for (int ni=0; ni<2; ni++)
                wmma::mma_sync(acc[mi][ni], af[mi], bf[ni], acc[mi][ni]);
        }
        __syncthreads();
    }

    #pragma unroll
    for (int mi=0; mi<4; mi++)
      #pragma unroll
      for (int ni=0; ni<2; ni++) {
        int r0 = mBase + wm*64 + mi*16;
        int c0 = nBase + wn*32 + ni*16;
        wmma::store_matrix_sync(&C[(size_t)r0*N + c0], acc[mi][ni], N, wmma::mem_row_major);
      }
}

// ===========================================================================
// Flash attention (tf32 wmma), QD=64, query tile 64, key tile 64.
// grid: (L/64, B*H), 256 threads (8 warps).
// ===========================================================================
__global__ __launch_bounds__(256) void attn_kernel()
{
    extern __shared__ float sm[];
    const int LD = 68;
    float* Qs  = sm;
    float* Ks  = sm + 64*LD;
    float* Vs  = sm + 2*64*LD;
    float* Ssm = sm + 3*64*LD;
    float* Osm = sm + 4*64*LD;

    const int tid   = threadIdx.x;
    const int w     = tid >> 5;
    const int wm    = w >> 1;      // 0..3 (rows 16)
    const int wn    = w & 1;       // 0..1 (cols 32)
    const int qtile = blockIdx.x;
    const int bh    = blockIdx.y;
    const int b     = bh / HH;
    const int h     = bh % HH;

    const size_t rowBase = (size_t)b * LL;
    const int colBase = h * QDIM;

    // load Q tile 64x64
    #pragma unroll
    for (int i=0;i<4;i++) {
        int f = tid + i*256;
        int r = f >> 4, c4 = f & 15;
        float4 val = *(const float4*)&g_q[(rowBase + qtile*64 + r)*DD + colBase + c4*4];
        *(float4*)&Qs[r*LD + c4*4] = val;
    }
    // zero O
    for (int i=tid; i<64*LD; i+=256) Osm[i] = 0.0f;
    __syncthreads();

    // per-row softmax state (4 threads per row; row = tid>>2, part = tid&3)
    const int srow = tid >> 2;
    const int part = tid & 3;
    float m_r = -INFINITY;
    float l_r = 0.0f;

    for (int kt = 0; kt < LL/64; kt++) {
        // load K, V tiles 64x64
        #pragma unroll
        for (int i=0;i<4;i++) {
            int f = tid + i*256;
            int r = f >> 4, c4 = f & 15;
            float4 kv = *(const float4*)&g_k[(rowBase + kt*64 + r)*DD + colBase + c4*4];
            *(float4*)&Ks[r*LD + c4*4] = kv;
            float4 vv = *(const float4*)&g_v[(rowBase + kt*64 + r)*DD + colBase + c4*4];
            *(float4*)&Vs[r*LD + c4*4] = vv;
        }
        __syncthreads();

        // S = Q @ K^T  (64x64x64)
        {
            wmma::fragment<wmma::accumulator, 16,16,8, float> sacc[2];
            wmma::fill_fragment(sacc[0], 0.0f);
            wmma::fill_fragment(sacc[1], 0.0f);
            #pragma unroll
            for (int kk=0; kk<8; kk++) {
                wmma::fragment<wmma::matrix_a, 16,16,8, wmma::precision::tf32, wmma::row_major> af;
                wmma::load_matrix_sync(af, &Qs[(wm*16)*LD + kk*8], LD);
                #pragma unroll
                for (int t=0; t<af.num_elements; t++) af.x[t] = wmma::__float_to_tf32(af.x[t]);
                #pragma unroll
                for (int ni=0; ni<2; ni++) {
                    wmma::fragment<wmma::matrix_b, 16,16,8, wmma::precision::tf32, wmma::col_major> bf;
                    wmma::load_matrix_sync(bf, &Ks[(wn*32 + ni*16)*LD + kk*8], LD);
                    #pragma unroll
                    for (int t=0; t<bf.num_elements; t++) bf.x[t] = wmma::__float_to_tf32(bf.x[t]);
                    wmma::mma_sync(sacc[ni], af, bf, sacc[ni]);
                }
            }
            #pragma unroll
            for (int ni=0; ni<2; ni++)
                wmma::store_matrix_sync(&Ssm[(wm*16)*LD + wn*32 + ni*16], sacc[ni], LD, wmma::mem_row_major);
        }
        __syncthreads();

        // online softmax update (SIMT): 4 threads per row, 16 cols each
        {
            float tmax = -INFINITY;
            #pragma unroll
            for (int c=0;c<16;c++) {
                float vsc = Ssm[srow*LD + part*16 + c] * ATT_SCALE;
                tmax = fmaxf(tmax, vsc);
            }
            tmax = fmaxf(tmax, __shfl_xor_sync(0xffffffffu, tmax, 1));
            tmax = fmaxf(tmax, __shfl_xor_sync(0xffffffffu, tmax, 2));
            float newm = fmaxf(m_r, tmax);
            float alpha = __expf(m_r - newm);
            float psum = 0.0f;
            #pragma unroll
            for (int c=0;c<16;c++) {
                float vsc = Ssm[srow*LD + part*16 + c] * ATT_SCALE;
                float p = __expf(vsc - newm);
                Ssm[srow*LD + part*16 + c] = p;
                psum += p;
            }
            psum += __shfl_xor_sync(0xffffffffu, psum, 1);
            psum += __shfl_xor_sync(0xffffffffu, psum, 2);
            l_r = l_r * alpha + psum;
            m_r = newm;
            #pragma unroll
            for (int c=0;c<16;c++)
                Osm[srow*LD + part*16 + c] *= alpha;
        }
        __syncthreads();

        // O += P @ V  (64x64x64), accumulate via load/store of Osm
        {
            #pragma unroll
            for (int ni=0; ni<2; ni++) {
                wmma::fragment<wmma::accumulator, 16,16,8, float> cfr;
                wmma::load_matrix_sync(cfr, &Osm[(wm*16)*LD + wn*32 + ni*16], LD, wmma::mem_row_major);
                #pragma unroll
                for (int kk=0; kk<8; kk++) {
                    wmma::fragment<wmma::matrix_a, 16,16,8, wmma::precision::tf32, wmma::row_major> af;
                    wmma::load_matrix_sync(af, &Ssm[(wm*16)*LD + kk*8], LD);
                    #pragma unroll
                    for (int t=0; t<af.num_elements; t++) af.x[t] = wmma::__float_to_tf32(af.x[t]);
                    wmma::fragment<wmma::matrix_b, 16,16,8, wmma::precision::tf32, wmma::row_major> bf;
                    wmma::load_matrix_sync(bf, &Vs[(kk*8)*LD + wn*32 + ni*16], LD);
                    #pragma unroll
                    for (int t=0; t<bf.num_elements; t++) bf.x[t] = wmma::__float_to_tf32(bf.x[t]);
                    wmma::mma_sync(cfr, af, bf, cfr);
                }
                wmma::store_matrix_sync(&Osm[(wm*16)*LD + wn*32 + ni*16], cfr, LD, wmma::mem_row_major);
            }
        }
        __syncthreads();
    }

    // write out: O / l
    float invl = 1.0f / l_r;
    #pragma unroll
    for (int c=0;c<16;c++) {
        g_att[(rowBase + qtile*64 + srow)*DD + colBase + part*16 + c] =
            Osm[srow*LD + part*16 + c] * invl;
    }
}

// ===========================================================================
// LayerNorm over D=512 of (in + bias + resid): one block per row, 128 threads
// ===========================================================================
__global__ __launch_bounds__(128) void ln_kernel(
    const float* __restrict__ in, const float* __restrict__ bias,
    const float* __restrict__ resid,
    const float* __restrict__ gamma, const float* __restrict__ beta,
    float* __restrict__ out)
{
    __shared__ float sh[8];
    const int row = blockIdx.x;
    const size_t base = (size_t)row * DD;
    float v[4];
    #pragma unroll
    for (int j=0;j<4;j++) {
        int c = threadIdx.x + j*128;
        v[j] = in[base + c] + bias[c] + resid[base + c];
    }
    float s = v[0]+v[1]+v[2]+v[3];
    #pragma unroll
    for (int o=16;o>0;o>>=1) s += __shfl_xor_sync(0xffffffffu, s, o);
    if ((threadIdx.x & 31)==0) sh[threadIdx.x>>5] = s;
    __syncthreads();
    float tot = sh[0]+sh[1]+sh[2]+sh[3];
    float mean = tot * (1.0f/DD);
    float sq = 0.0f;
    #pragma unroll
    for (int j=0;j<4;j++) { float d = v[j]-mean; sq += d*d; }
    #pragma unroll
    for (int o=16;o>0;o>>=1) sq += __shfl_xor_sync(0xffffffffu, sq, o);
    __syncthreads();
    if ((threadIdx.x & 31)==0) sh[4 + (threadIdx.x>>5)] = sq;
    __syncthreads();
    float var = (sh[4]+sh[5]+sh[6]+sh[7]) * (1.0f/DD);
    float rstd = rsqrtf(var + EPS);
    #pragma unroll
    for (int j=0;j<4;j++) {
        int c = threadIdx.x + j*128;
        out[base + c] = (v[j]-mean)*rstd*gamma[c] + beta[c];
    }
}

// ===========================================================================
// bias + relu elementwise on [MTOT, FFD]
// ===========================================================================
__global__ __launch_bounds__(256) void bias_relu_kernel(
    float* __restrict__ hbuf, const float* __restrict__ b1)
{
    const size_t n4 = (size_t)MTOT * FFD / 4;
    for (size_t i = blockIdx.x*blockDim.x + threadIdx.x; i < n4; i += (size_t)gridDim.x*blockDim.x) {
        float4 val = *(float4*)&hbuf[i*4];
        int col = (int)((i*4) % FFD);
        val.x = fmaxf(val.x + b1[col+0], 0.0f);
        val.y = fmaxf(val.y + b1[col+1], 0.0f);
        val.z = fmaxf(val.z + b1[col+2], 0.0f);
        val.w = fmaxf(val.w + b1[col+3], 0.0f);
        *(float4*)&hbuf[i*4] = val;
    }
}

// ===========================================================================
extern "C" void kernel_launch(void* const* d_in, const int* in_sizes, int n_in,
                              void* d_out, int out_size)
{
    const float* x     = (const float*)d_in[0];
    const float* WQ    = (const float*)d_in[1];
    const float* WK    = (const float*)d_in[2];
    const float* WV    = (const float*)d_in[3];
    const float* WZ    = (const float*)d_in[4];
    const float* bZ    = (const float*)d_in[5];
    const float* W1    = (const float*)d_in[6];
    const float* b1    = (const float*)d_in[7];
    const float* W2    = (const float*)d_in[8];
    const float* b2    = (const float*)d_in[9];
    const float* gamma = (const float*)d_in[10];
    const float* beta  = (const float*)d_in[11];
    float* out = (float*)d_out;

    float *q, *k, *v, *att, *t1, *zn, *hbuf, *o2;
    cudaGetSymbolAddress((void**)&q,   g_q);
    cudaGetSymbolAddress((void**)&k,   g_k);
    cudaGetSymbolAddress((void**)&v,   g_v);
    cudaGetSymbolAddress((void**)&att, g_att);
    cudaGetSymbolAddress((void**)&t1,  g_t1);
    cudaGetSymbolAddress((void**)&zn,  g_zn);
    cudaGetSymbolAddress((void**)&hbuf,g_h);
    cudaGetSymbolAddress((void**)&o2,  g_o2);

    const int attn_smem = 5 * 64 * 68 * 4;  // 87040 B
    cudaFuncSetAttribute(attn_kernel, cudaFuncAttributeMaxDynamicSharedMemorySize, attn_smem);

    dim3 gThr(256);
    // QKV projections
    gemm_tf32_kernel<<<dim3(DD/128,  MTOT/128), gThr>>>(x, WQ, q, MTOT, DD, DD);
    gemm_tf32_kernel<<<dim3(DD/128,  MTOT/128), gThr>>>(x, WK, k, MTOT, DD, DD);
    gemm_tf32_kernel<<<dim3(DD/128,  MTOT/128), gThr>>>(x, WV, v, MTOT, DD, DD);
    // attention
    attn_kernel<<<dim3(LL/64, BB*HH), gThr, attn_smem>>>();
    // z @ WZ
    gemm_tf32_kernel<<<dim3(DD/128,  MTOT/128), gThr>>>(att, WZ, t1, MTOT, DD, DD);
    // LN1: LN(t1 + bZ + x)
    ln_kernel<<<MTOT, 128>>>(t1, bZ, x, gamma, beta, zn);
    // FF
    gemm_tf32_kernel<<<dim3(FFD/128, MTOT/128), gThr>>>(zn, W1, hbuf, MTOT, FFD, DD);
    bias_relu_kernel<<<4096, 256>>>(hbuf, b1);
    gemm_tf32_kernel<<<dim3(DD/128,  MTOT/128), gThr>>>(hbuf, W2, o2, MTOT, DD, FFD);
    // LN2: LN(o2 + b2 + zn) -> out
    ln_kernel<<<MTOT, 128>>>(o2, b2, zn, gamma, beta, out);
}

// round 2
// speedup vs baseline: 1.5782x; 1.5782x over previous
#include <cuda_runtime.h>
#include <mma.h>
#include <math.h>
#include <stdint.h>

using namespace nvcuda;

// Problem constants
#define BB 4
#define LL 2048
#define DD 512
#define HH 8
#define QDIM 64
#define FFD 2048
#define MTOT (BB*LL)          // 8192
#define EPS 1e-5f
#define ATT_SCALE 0.125f      // 1/sqrt(64)

// -------------------- scratch (device globals; no allocation allowed) -----
__device__ float g_q  [MTOT*DD];
__device__ float g_k  [MTOT*DD];
__device__ float g_v  [MTOT*DD];
__device__ float g_att[MTOT*DD];
__device__ float g_t1 [MTOT*DD];
__device__ float g_zn [MTOT*DD];
__device__ float g_h  [MTOT*FFD];
__device__ float g_o2 [MTOT*DD];

// -------------------- small PTX helpers ----------------------------------
__device__ __forceinline__ void cp16(float* s, const float* g) {
    uint32_t sa = (uint32_t)__cvta_generic_to_shared(s);
    asm volatile("cp.async.cg.shared.global [%0], [%1], 16;\n" :: "r"(sa), "l"(g));
}
__device__ __forceinline__ void cp_commit() { asm volatile("cp.async.commit_group;\n"); }
template<int N> __device__ __forceinline__ void cp_wait() {
    asm volatile("cp.async.wait_group %0;\n" :: "n"(N));
}
__device__ __forceinline__ uint32_t tf32r(float x) {
    uint32_t u; asm("cvt.rna.tf32.f32 %0, %1;" : "=r"(u) : "f"(x)); return u;
}
// D += A @ B, m16n8k8 tf32, row.col
__device__ __forceinline__ void mma8(float* d, const uint32_t* a, uint32_t b0, uint32_t b1) {
    asm volatile("mma.sync.aligned.m16n8k8.row.col.f32.tf32.tf32.f32 "
        "{%0,%1,%2,%3}, {%4,%5,%6,%7}, {%8,%9}, {%0,%1,%2,%3};\n"
        : "+f"(d[0]), "+f"(d[1]), "+f"(d[2]), "+f"(d[3])
        : "r"(a[0]), "r"(a[1]), "r"(a[2]), "r"(a[3]), "r"(b0), "r"(b1));
}

// ===========================================================================
// 3-stage cp.async pipelined tf32 GEMM: C[M,N] = A[M,K] @ B[K,N]
// Block tile 128x128, BK=32, 256 threads, warp tile 64x32.
// ===========================================================================
#define GA_LD 36
#define GB_LD 132
#define GA_SZ (128*GA_LD)
#define GB_SZ (32*GB_LD)
#define GSTG 3
#define GEMM_SMEM (GSTG*(GA_SZ+GB_SZ)*4)

__device__ __forceinline__ void gemm_body(
    const float* __restrict__ A, const float* __restrict__ B, float* __restrict__ C,
    int M, int N, int K, float* sm, int mBase, int nBase)
{
    float* As = sm;
    float* Bs = sm + GSTG*GA_SZ;
    const int tid = threadIdx.x;
    const int w = tid >> 5, wm = w >> 2, wn = w & 3;

    auto load_stage = [&](int st, int k0) {
        float* as = As + st*GA_SZ;
        float* bs = Bs + st*GB_SZ;
        #pragma unroll
        for (int i=0;i<4;i++){
            int f = tid + i*256;
            int r = f >> 3, c4 = f & 7;
            cp16(&as[r*GA_LD + c4*4], &A[(size_t)(mBase+r)*K + k0 + c4*4]);
        }
        #pragma unroll
        for (int i=0;i<4;i++){
            int f = tid + i*256;
            int r = f >> 5, c4 = f & 31;
            cp16(&bs[r*GB_LD + c4*4], &B[(size_t)(k0+r)*N + nBase + c4*4]);
        }
        cp_commit();
    };

    wmma::fragment<wmma::accumulator,16,16,8,float> acc[4][2];
    #pragma unroll
    for (int mi=0;mi<4;mi++)
        #pragma unroll
        for (int ni=0;ni<2;ni++) wmma::fill_fragment(acc[mi][ni], 0.0f);

    const int nk = K/32;
    load_stage(0, 0);
    load_stage(1, 32);

    for (int kt=0; kt<nk; kt++){
        cp_wait<1>();
        __syncthreads();
        if (kt+2 < nk) load_stage((kt+2)%GSTG, (kt+2)*32);

        float* as = As + (kt%GSTG)*GA_SZ;
        float* bs = Bs + (kt%GSTG)*GB_SZ;
        #pragma unroll
        for (int kk=0;kk<4;kk++){
            wmma::fragment<wmma::matrix_a,16,16,8,wmma::precision::tf32,wmma::row_major> af[4];
            wmma::fragment<wmma::matrix_b,16,16,8,wmma::precision::tf32,wmma::row_major> bf[2];
            #pragma unroll
            for (int mi=0;mi<4;mi++)
                wmma::load_matrix_sync(af[mi], &as[(wm*64+mi*16)*GA_LD + kk*8], GA_LD);
            #pragma unroll
            for (int ni=0;ni<2;ni++)
                wmma::load_matrix_sync(bf[ni], &bs[(kk*8)*GB_LD + wn*32 + ni*16], GB_LD);
            // no cvt: hardware reads tf32 bits (truncation) — saves FFMA-pipe work
            #pragma unroll
            for (int mi=0;mi<4;mi++)
                #pragma unroll
                for (int ni=0;ni<2;ni++)
                    wmma::mma_sync(acc[mi][ni], af[mi], bf[ni], acc[mi][ni]);
        }
        __syncthreads();
    }

    #pragma unroll
    for (int mi=0;mi<4;mi++)
        #pragma unroll
        for (int ni=0;ni<2;ni++){
            int r0 = mBase + wm*64 + mi*16;
            int c0 = nBase + wn*32 + ni*16;
            wmma::store_matrix_sync(&C[(size_t)r0*N + c0], acc[mi][ni], N, wmma::mem_row_major);
        }
}

__global__ __launch_bounds__(256) void gemm_k(
    const float* __restrict__ A, const float* __restrict__ B, float* __restrict__ C,
    int M, int N, int K)
{
    extern __shared__ float sm[];
    gemm_body(A, B, C, M, N, K, sm, blockIdx.y*128, blockIdx.x*128);
}

__global__ __launch_bounds__(256) void gemm_qkv_k(
    const float* __restrict__ A,
    const float* __restrict__ B0, const float* __restrict__ B1, const float* __restrict__ B2,
    float* __restrict__ C0, float* __restrict__ C1, float* __restrict__ C2,
    int M, int N, int K)
{
    extern __shared__ float sm[];
    const float* B = (blockIdx.z==0) ? B0 : (blockIdx.z==1 ? B1 : B2);
    float*       C = (blockIdx.z==0) ? C0 : (blockIdx.z==1 ? C1 : C2);
    gemm_body(A, B, C, M, N, K, sm, blockIdx.y*128, blockIdx.x*128);
}

// ===========================================================================
// Flash attention, explicit mma.m16n8k8.tf32, register-resident S and O.
// Block: 128 threads (4 warps); warp w owns query rows [w*16, w*16+16).
// smem: Qs (reused as Ps after Q frags cached), Ks, Vs — 64 x ALD each.
// ===========================================================================
#define ALD 72
#define ATT_SMEM (3*64*ALD*4)

__global__ __launch_bounds__(128) void attn_kernel()
{
    extern __shared__ float sm[];
    float* Qs = sm;               // reused as Ps after Q frags load
    float* Ks = sm + 64*ALD;
    float* Vs = sm + 2*64*ALD;

    const int tid  = threadIdx.x;
    const int w    = tid >> 5, lane = tid & 31;
    const int g    = lane >> 2, tig = lane & 3;
    const int qtile = blockIdx.x, bh = blockIdx.y;
    const int b    = bh >> 3, h = bh & 7;
    const size_t rowBase = (size_t)b * LL;
    const int colBase = h * QDIM;
    const int qrow0 = qtile * 64;
    const int pr = w*16 + g;      // this thread's base P/O row in the 64-row tile

    // load Q tile 64x64
    #pragma unroll
    for (int i=0;i<8;i++){
        int f = tid + i*128;
        int r = f >> 4, c4 = f & 15;
        cp16(&Qs[r*ALD + c4*4], &g_q[(rowBase+qrow0+r)*DD + colBase + c4*4]);
    }
    cp_commit(); cp_wait<0>(); __syncthreads();

    // persistent Q A-fragments (rounded to tf32 once)
    uint32_t qf[8][4];
    #pragma unroll
    for (int kk=0;kk<8;kk++){
        qf[kk][0] = tf32r(Qs[ pr      *ALD + kk*8 + tig    ]);
        qf[kk][1] = tf32r(Qs[(pr+8)   *ALD + kk*8 + tig    ]);
        qf[kk][2] = tf32r(Qs[ pr      *ALD + kk*8 + tig + 4]);
        qf[kk][3] = tf32r(Qs[(pr+8)   *ALD + kk*8 + tig + 4]);
    }

    float o[8][4];
    #pragma unroll
    for (int n=0;n<8;n++){ o[n][0]=o[n][1]=o[n][2]=o[n][3]=0.f; }
    float m0=-1e30f, m1=-1e30f, l0=0.f, l1=0.f;

    for (int kt=0; kt<LL/64; kt++){
        __syncthreads();   // all warps done with prior Ks/Vs (and Qs for kt==0)
        #pragma unroll
        for (int i=0;i<8;i++){
            int f = tid + i*128;
            int r = f >> 4, c4 = f & 15;
            cp16(&Ks[r*ALD + c4*4], &g_k[(rowBase+kt*64+r)*DD + colBase + c4*4]);
            cp16(&Vs[r*ALD + c4*4], &g_v[(rowBase+kt*64+r)*DD + colBase + c4*4]);
        }
        cp_commit(); cp_wait<0>(); __syncthreads();

        // S = Q @ K^T  (16x64 per warp), registers only
        float s[8][4];
        #pragma unroll
        for (int n=0;n<8;n++){ s[n][0]=s[n][1]=s[n][2]=s[n][3]=0.f; }
        #pragma unroll
        for (int kk=0;kk<8;kk++){
            #pragma unroll
            for (int n=0;n<8;n++){
                uint32_t b0 = __float_as_uint(Ks[(n*8+g)*ALD + kk*8 + tig    ]);
                uint32_t b1 = __float_as_uint(Ks[(n*8+g)*ALD + kk*8 + tig + 4]);
                mma8(s[n], qf[kk], b0, b1);
            }
        }

        // online softmax, fully in registers (rows g / g+8; quad reduction)
        float mx0=-1e30f, mx1=-1e30f;
        #pragma unroll
        for (int n=0;n<8;n++){
            mx0 = fmaxf(mx0, fmaxf(s[n][0], s[n][1]));
            mx1 = fmaxf(mx1, fmaxf(s[n][2], s[n][3]));
        }
        mx0 = fmaxf(mx0, __shfl_xor_sync(0xffffffffu, mx0, 1));
        mx0 = fmaxf(mx0, __shfl_xor_sync(0xffffffffu, mx0, 2));
        mx1 = fmaxf(mx1, __shfl_xor_sync(0xffffffffu, mx1, 1));
        mx1 = fmaxf(mx1, __shfl_xor_sync(0xffffffffu, mx1, 2));
        float nm0 = fmaxf(m0, mx0*ATT_SCALE);
        float nm1 = fmaxf(m1, mx1*ATT_SCALE);
        float a0 = __expf(m0 - nm0), a1 = __expf(m1 - nm1);
        float sum0 = 0.f, sum1 = 0.f;
        #pragma unroll
        for (int n=0;n<8;n++){
            s[n][0] = __expf(s[n][0]*ATT_SCALE - nm0);
            s[n][1] = __expf(s[n][1]*ATT_SCALE - nm0);
            s[n][2] = __expf(s[n][2]*ATT_SCALE - nm1);
            s[n][3] = __expf(s[n][3]*ATT_SCALE - nm1);
            sum0 += s[n][0] + s[n][1];
            sum1 += s[n][2] + s[n][3];
        }
        sum0 += __shfl_xor_sync(0xffffffffu, sum0, 1);
        sum0 += __shfl_xor_sync(0xffffffffu, sum0, 2);
        sum1 += __shfl_xor_sync(0xffffffffu, sum1, 1);
        sum1 += __shfl_xor_sync(0xffffffffu, sum1, 2);
        l0 = l0*a0 + sum0;  l1 = l1*a1 + sum1;
        m0 = nm0;  m1 = nm1;
        #pragma unroll
        for (int n=0;n<8;n++){
            o[n][0]*=a0; o[n][1]*=a0; o[n][2]*=a1; o[n][3]*=a1;
        }

        // P -> warp-private smem slab (C-layout to A-layout shuffle)
        #pragma unroll
        for (int n=0;n<8;n++){
            *(float2*)&Qs[ pr   *ALD + n*8 + 2*tig] = make_float2(s[n][0], s[n][1]);
            *(float2*)&Qs[(pr+8)*ALD + n*8 + 2*tig] = make_float2(s[n][2], s[n][3]);
        }
        __syncwarp();

        // O += P @ V
        #pragma unroll
        for (int kk=0;kk<8;kk++){
            uint32_t pa[4];
            pa[0] = __float_as_uint(Qs[ pr   *ALD + kk*8 + tig    ]);
            pa[1] = __float_as_uint(Qs[(pr+8)*ALD + kk*8 + tig    ]);
            pa[2] = __float_as_uint(Qs[ pr   *ALD + kk*8 + tig + 4]);
            pa[3] = __float_as_uint(Qs[(pr+8)*ALD + kk*8 + tig + 4]);
            #pragma unroll
            for (int n=0;n<8;n++){
                uint32_t b0 = __float_as_uint(Vs[(kk*8+tig  )*ALD + n*8 + g]);
                uint32_t b1 = __float_as_uint(Vs[(kk*8+tig+4)*ALD + n*8 + g]);
                mma8(o[n], pa, b0, b1);
            }
        }
    }

    // normalize and write out (float2, C-layout cols adjacent)
    float inv0 = 1.f/l0, inv1 = 1.f/l1;
    const int r0 = qrow0 + pr;
    #pragma unroll
    for (int n=0;n<8;n++){
        *(float2*)&g_att[(rowBase + r0    )*DD + colBase + n*8 + 2*tig] =
            make_float2(o[n][0]*inv0, o[n][1]*inv0);
        *(float2*)&g_att[(rowBase + r0 + 8)*DD + colBase + n*8 + 2*tig] =
            make_float2(o[n][2]*inv1, o[n][3]*inv1);
    }
}

// ===========================================================================
// LayerNorm over D=512 of (in + bias + resid): one block per row, 128 threads
// ===========================================================================
__global__ __launch_bounds__(128) void ln_kernel(
    const float* __restrict__ in, const float* __restrict__ bias,
    const float* __restrict__ resid,
    const float* __restrict__ gamma, const float* __restrict__ beta,
    float* __restrict__ out)
{
    __shared__ float sh[8];
    const int row = blockIdx.x;
    const size_t base = (size_t)row * DD;
    float v[4];
    #pragma unroll
    for (int j=0;j<4;j++){
        int c = threadIdx.x + j*128;
        v[j] = in[base + c] + bias[c] + resid[base + c];
    }
    float s = v[0]+v[1]+v[2]+v[3];
    #pragma unroll
    for (int o=16;o>0;o>>=1) s += __shfl_xor_sync(0xffffffffu, s, o);
    if ((threadIdx.x & 31)==0) sh[threadIdx.x>>5] = s;
    __syncthreads();
    float mean = (sh[0]+sh[1]+sh[2]+sh[3]) * (1.0f/DD);
    float sq = 0.0f;
    #pragma unroll
    for (int j=0;j<4;j++){ float d = v[j]-mean; sq += d*d; }
    #pragma unroll
    for (int o=16;o>0;o>>=1) sq += __shfl_xor_sync(0xffffffffu, sq, o);
    __syncthreads();
    if ((threadIdx.x & 31)==0) sh[4 + (threadIdx.x>>5)] = sq;
    __syncthreads();
    float var = (sh[4]+sh[5]+sh[6]+sh[7]) * (1.0f/DD);
    float rstd = rsqrtf(var + EPS);
    #pragma unroll
    for (int j=0;j<4;j++){
        int c = threadIdx.x + j*128;
        out[base + c] = (v[j]-mean)*rstd*gamma[c] + beta[c];
    }
}

// ===========================================================================
// bias + relu elementwise on [MTOT, FFD]
// ===========================================================================
__global__ __launch_bounds__(256) void bias_relu_kernel(
    float* __restrict__ hbuf, const float* __restrict__ b1)
{
    const size_t n4 = (size_t)MTOT * FFD / 4;
    for (size_t i = blockIdx.x*blockDim.x + threadIdx.x; i < n4; i += (size_t)gridDim.x*blockDim.x){
        float4 val = *(float4*)&hbuf[i*4];
        int col = (int)((i*4) % FFD);
        val.x = fmaxf(val.x + b1[col+0], 0.0f);
        val.y = fmaxf(val.y + b1[col+1], 0.0f);
        val.z = fmaxf(val.z + b1[col+2], 0.0f);
        val.w = fmaxf(val.w + b1[col+3], 0.0f);
        *(float4*)&hbuf[i*4] = val;
    }
}

// ===========================================================================
extern "C" void kernel_launch(void* const* d_in, const int* in_sizes, int n_in,
                              void* d_out, int out_size)
{
    const float* x     = (const float*)d_in[0];
    const float* WQ    = (const float*)d_in[1];
    const float* WK    = (const float*)d_in[2];
    const float* WV    = (const float*)d_in[3];
    const float* WZ    = (const float*)d_in[4];
    const float* bZ    = (const float*)d_in[5];
    const float* W1    = (const float*)d_in[6];
    const float* b1    = (const float*)d_in[7];
    const float* W2    = (const float*)d_in[8];
    const float* b2    = (const float*)d_in[9];
    const float* gamma = (const float*)d_in[10];
    const float* beta  = (const float*)d_in[11];
    float* out = (float*)d_out;

    float *q, *k, *v, *att, *t1, *zn, *hbuf, *o2;
    cudaGetSymbolAddress((void**)&q,    g_q);
    cudaGetSymbolAddress((void**)&k,    g_k);
    cudaGetSymbolAddress((void**)&v,    g_v);
    cudaGetSymbolAddress((void**)&att,  g_att);
    cudaGetSymbolAddress((void**)&t1,   g_t1);
    cudaGetSymbolAddress((void**)&zn,   g_zn);
    cudaGetSymbolAddress((void**)&hbuf, g_h);
    cudaGetSymbolAddress((void**)&o2,   g_o2);

    cudaFuncSetAttribute(gemm_k,     cudaFuncAttributeMaxDynamicSharedMemorySize, GEMM_SMEM);
    cudaFuncSetAttribute(gemm_qkv_k, cudaFuncAttributeMaxDynamicSharedMemorySize, GEMM_SMEM);
    cudaFuncSetAttribute(attn_kernel,cudaFuncAttributeMaxDynamicSharedMemorySize, ATT_SMEM);

    // QKV projections (batched in one launch via gridDim.z)
    gemm_qkv_k<<<dim3(DD/128, MTOT/128, 3), 256, GEMM_SMEM>>>(x, WQ, WK, WV, q, k, v, MTOT, DD, DD);
    // attention
    attn_kernel<<<dim3(LL/64, BB*HH), 128, ATT_SMEM>>>();
    // z @ WZ
    gemm_k<<<dim3(DD/128, MTOT/128), 256, GEMM_SMEM>>>(att, WZ, t1, MTOT, DD, DD);
    // LN1: LN(t1 + bZ + x)
    ln_kernel<<<MTOT, 128>>>(t1, bZ, x, gamma, beta, zn);
    // FF
    gemm_k<<<dim3(FFD/128, MTOT/128), 256, GEMM_SMEM>>>(zn, W1, hbuf, MTOT, FFD, DD);
    bias_relu_kernel<<<4096, 256>>>(hbuf, b1);
    gemm_k<<<dim3(DD/128, MTOT/128), 256, GEMM_SMEM>>>(hbuf, W2, o2, MTOT, DD, FFD);
    // LN2: LN(o2 + b2 + zn) -> out
    ln_kernel<<<MTOT, 128>>>(o2, b2, zn, gamma, beta, out);
}

// round 3
// speedup vs baseline: 1.5802x; 1.0012x over previous
#include <cuda_runtime.h>
#include <mma.h>
#include <math.h>
#include <stdint.h>

using namespace nvcuda;

// Problem constants
#define BB 4
#define LL 2048
#define DD 512
#define HH 8
#define QDIM 64
#define FFD 2048
#define MTOT (BB*LL)          // 8192
#define EPS 1e-5f
#define ATT_SCALE 0.125f      // 1/sqrt(64)

// -------------------- scratch (device globals; no allocation allowed) -----
__device__ float g_q  [MTOT*DD];
__device__ float g_k  [MTOT*DD];
__device__ float g_v  [MTOT*DD];
__device__ float g_att[MTOT*DD];
__device__ float g_t1 [MTOT*DD];
__device__ float g_zn [MTOT*DD];
__device__ float g_h  [MTOT*FFD];
__device__ float g_o2 [MTOT*DD];

// -------------------- small PTX helpers ----------------------------------
__device__ __forceinline__ void cp16(float* s, const float* g) {
    uint32_t sa = (uint32_t)__cvta_generic_to_shared(s);
    asm volatile("cp.async.cg.shared.global [%0], [%1], 16;\n" :: "r"(sa), "l"(g));
}
__device__ __forceinline__ void cp_commit() { asm volatile("cp.async.commit_group;\n"); }
template<int N> __device__ __forceinline__ void cp_wait() {
    asm volatile("cp.async.wait_group %0;\n" :: "n"(N));
}
__device__ __forceinline__ uint32_t tf32r(float x) {
    uint32_t u; asm("cvt.rna.tf32.f32 %0, %1;" : "=r"(u) : "f"(x)); return u;
}
// D += A @ B, m16n8k8 tf32, row.col
__device__ __forceinline__ void mma8(float* d, const uint32_t* a, uint32_t b0, uint32_t b1) {
    asm volatile("mma.sync.aligned.m16n8k8.row.col.f32.tf32.tf32.f32 "
        "{%0,%1,%2,%3}, {%4,%5,%6,%7}, {%8,%9}, {%0,%1,%2,%3};\n"
        : "+f"(d[0]), "+f"(d[1]), "+f"(d[2]), "+f"(d[3])
        : "r"(a[0]), "r"(a[1]), "r"(a[2]), "r"(a[3]), "r"(b0), "r"(b1));
}

// ===========================================================================
// 3-stage cp.async pipelined tf32 GEMM: C[M,N] = A[M,K] @ B[K,N]
// Block tile 128x128, BK=32, 256 threads, warp tile 64x32.
// ===========================================================================
#define GA_LD 36
#define GB_LD 132
#define GA_SZ (128*GA_LD)
#define GB_SZ (32*GB_LD)
#define GSTG 3
#define GEMM_SMEM (GSTG*(GA_SZ+GB_SZ)*4)

__device__ __forceinline__ void gemm_body(
    const float* __restrict__ A, const float* __restrict__ B, float* __restrict__ C,
    int M, int N, int K, float* sm, int mBase, int nBase)
{
    float* As = sm;
    float* Bs = sm + GSTG*GA_SZ;
    const int tid = threadIdx.x;
    const int w = tid >> 5, wm = w >> 2, wn = w & 3;

    auto load_stage = [&](int st, int k0) {
        float* as = As + st*GA_SZ;
        float* bs = Bs + st*GB_SZ;
        #pragma unroll
        for (int i=0;i<4;i++){
            int f = tid + i*256;
            int r = f >> 3, c4 = f & 7;
            cp16(&as[r*GA_LD + c4*4], &A[(size_t)(mBase+r)*K + k0 + c4*4]);
        }
        #pragma unroll
        for (int i=0;i<4;i++){
            int f = tid + i*256;
            int r = f >> 5, c4 = f & 31;
            cp16(&bs[r*GB_LD + c4*4], &B[(size_t)(k0+r)*N + nBase + c4*4]);
        }
        cp_commit();
    };

    wmma::fragment<wmma::accumulator,16,16,8,float> acc[4][2];
    #pragma unroll
    for (int mi=0;mi<4;mi++)
        #pragma unroll
        for (int ni=0;ni<2;ni++) wmma::fill_fragment(acc[mi][ni], 0.0f);

    const int nk = K/32;
    load_stage(0, 0);
    load_stage(1, 32);

    for (int kt=0; kt<nk; kt++){
        cp_wait<1>();
        __syncthreads();
        if (kt+2 < nk) load_stage((kt+2)%GSTG, (kt+2)*32);

        float* as = As + (kt%GSTG)*GA_SZ;
        float* bs = Bs + (kt%GSTG)*GB_SZ;
        #pragma unroll
        for (int kk=0;kk<4;kk++){
            wmma::fragment<wmma::matrix_a,16,16,8,wmma::precision::tf32,wmma::row_major> af[4];
            wmma::fragment<wmma::matrix_b,16,16,8,wmma::precision::tf32,wmma::row_major> bf[2];
            #pragma unroll
            for (int mi=0;mi<4;mi++)
                wmma::load_matrix_sync(af[mi], &as[(wm*64+mi*16)*GA_LD + kk*8], GA_LD);
            #pragma unroll
            for (int ni=0;ni<2;ni++)
                wmma::load_matrix_sync(bf[ni], &bs[(kk*8)*GB_LD + wn*32 + ni*16], GB_LD);
            // no cvt: hardware reads tf32 bits (truncation) — saves FFMA-pipe work
            #pragma unroll
            for (int mi=0;mi<4;mi++)
                #pragma unroll
                for (int ni=0;ni<2;ni++)
                    wmma::mma_sync(acc[mi][ni], af[mi], bf[ni], acc[mi][ni]);
        }
        __syncthreads();
    }

    #pragma unroll
    for (int mi=0;mi<4;mi++)
        #pragma unroll
        for (int ni=0;ni<2;ni++){
            int r0 = mBase + wm*64 + mi*16;
            int c0 = nBase + wn*32 + ni*16;
            wmma::store_matrix_sync(&C[(size_t)r0*N + c0], acc[mi][ni], N, wmma::mem_row_major);
        }
}

__global__ __launch_bounds__(256) void gemm_k(
    const float* __restrict__ A, const float* __restrict__ B, float* __restrict__ C,
    int M, int N, int K)
{
    extern __shared__ float sm[];
    gemm_body(A, B, C, M, N, K, sm, blockIdx.y*128, blockIdx.x*128);
}

__global__ __launch_bounds__(256) void gemm_qkv_k(
    const float* __restrict__ A,
    const float* __restrict__ B0, const float* __restrict__ B1, const float* __restrict__ B2,
    float* __restrict__ C0, float* __restrict__ C1, float* __restrict__ C2,
    int M, int N, int K)
{
    extern __shared__ float sm[];
    const float* B = (blockIdx.z==0) ? B0 : (blockIdx.z==1 ? B1 : B2);
    float*       C = (blockIdx.z==0) ? C0 : (blockIdx.z==1 ? C1 : C2);
    gemm_body(A, B, C, M, N, K, sm, blockIdx.y*128, blockIdx.x*128);
}

// ===========================================================================
// Flash attention, explicit mma.m16n8k8.tf32, register-resident S and O.
// Block: 128 threads (4 warps); warp w owns query rows [w*16, w*16+16).
// smem: Qs (reused as Ps after Q frags cached), Ks, Vs — 64 x ALD each.
// ===========================================================================
#define ALD 72
#define ATT_SMEM (3*64*ALD*4)

__global__ __launch_bounds__(128) void attn_kernel()
{
    extern __shared__ float sm[];
    float* Qs = sm;               // reused as Ps after Q frags load
    float* Ks = sm + 64*ALD;
    float* Vs = sm + 2*64*ALD;

    const int tid  = threadIdx.x;
    const int w    = tid >> 5, lane = tid & 31;
    const int g    = lane >> 2, tig = lane & 3;
    const int qtile = blockIdx.x, bh = blockIdx.y;
    const int b    = bh >> 3, h = bh & 7;
    const size_t rowBase = (size_t)b * LL;
    const int colBase = h * QDIM;
    const int qrow0 = qtile * 64;
    const int pr = w*16 + g;      // this thread's base P/O row in the 64-row tile

    // load Q tile 64x64
    #pragma unroll
    for (int i=0;i<8;i++){
        int f = tid + i*128;
        int r = f >> 4, c4 = f & 15;
        cp16(&Qs[r*ALD + c4*4], &g_q[(rowBase+qrow0+r)*DD + colBase + c4*4]);
    }
    cp_commit(); cp_wait<0>(); __syncthreads();

    // persistent Q A-fragments (rounded to tf32 once)
    uint32_t qf[8][4];
    #pragma unroll
    for (int kk=0;kk<8;kk++){
        qf[kk][0] = tf32r(Qs[ pr      *ALD + kk*8 + tig    ]);
        qf[kk][1] = tf32r(Qs[(pr+8)   *ALD + kk*8 + tig    ]);
        qf[kk][2] = tf32r(Qs[ pr      *ALD + kk*8 + tig + 4]);
        qf[kk][3] = tf32r(Qs[(pr+8)   *ALD + kk*8 + tig + 4]);
    }

    float o[8][4];
    #pragma unroll
    for (int n=0;n<8;n++){ o[n][0]=o[n][1]=o[n][2]=o[n][3]=0.f; }
    float m0=-1e30f, m1=-1e30f, l0=0.f, l1=0.f;

    for (int kt=0; kt<LL/64; kt++){
        __syncthreads();   // all warps done with prior Ks/Vs (and Qs for kt==0)
        #pragma unroll
        for (int i=0;i<8;i++){
            int f = tid + i*128;
            int r = f >> 4, c4 = f & 15;
            cp16(&Ks[r*ALD + c4*4], &g_k[(rowBase+kt*64+r)*DD + colBase + c4*4]);
            cp16(&Vs[r*ALD + c4*4], &g_v[(rowBase+kt*64+r)*DD + colBase + c4*4]);
        }
        cp_commit(); cp_wait<0>(); __syncthreads();

        // S = Q @ K^T  (16x64 per warp), registers only
        float s[8][4];
        #pragma unroll
        for (int n=0;n<8;n++){ s[n][0]=s[n][1]=s[n][2]=s[n][3]=0.f; }
        #pragma unroll
        for (int kk=0;kk<8;kk++){
            #pragma unroll
            for (int n=0;n<8;n++){
                uint32_t b0 = __float_as_uint(Ks[(n*8+g)*ALD + kk*8 + tig    ]);
                uint32_t b1 = __float_as_uint(Ks[(n*8+g)*ALD + kk*8 + tig + 4]);
                mma8(s[n], qf[kk], b0, b1);
            }
        }

        // online softmax, fully in registers (rows g / g+8; quad reduction)
        float mx0=-1e30f, mx1=-1e30f;
        #pragma unroll
        for (int n=0;n<8;n++){
            mx0 = fmaxf(mx0, fmaxf(s[n][0], s[n][1]));
            mx1 = fmaxf(mx1, fmaxf(s[n][2], s[n][3]));
        }
        mx0 = fmaxf(mx0, __shfl_xor_sync(0xffffffffu, mx0, 1));
        mx0 = fmaxf(mx0, __shfl_xor_sync(0xffffffffu, mx0, 2));
        mx1 = fmaxf(mx1, __shfl_xor_sync(0xffffffffu, mx1, 1));
        mx1 = fmaxf(mx1, __shfl_xor_sync(0xffffffffu, mx1, 2));
        float nm0 = fmaxf(m0, mx0*ATT_SCALE);
        float nm1 = fmaxf(m1, mx1*ATT_SCALE);
        float a0 = __expf(m0 - nm0), a1 = __expf(m1 - nm1);
        float sum0 = 0.f, sum1 = 0.f;
        #pragma unroll
        for (int n=0;n<8;n++){
            s[n][0] = __expf(s[n][0]*ATT_SCALE - nm0);
            s[n][1] = __expf(s[n][1]*ATT_SCALE - nm0);
            s[n][2] = __expf(s[n][2]*ATT_SCALE - nm1);
            s[n][3] = __expf(s[n][3]*ATT_SCALE - nm1);
            sum0 += s[n][0] + s[n][1];
            sum1 += s[n][2] + s[n][3];
        }
        sum0 += __shfl_xor_sync(0xffffffffu, sum0, 1);
        sum0 += __shfl_xor_sync(0xffffffffu, sum0, 2);
        sum1 += __shfl_xor_sync(0xffffffffu, sum1, 1);
        sum1 += __shfl_xor_sync(0xffffffffu, sum1, 2);
        l0 = l0*a0 + sum0;  l1 = l1*a1 + sum1;
        m0 = nm0;  m1 = nm1;
        #pragma unroll
        for (int n=0;n<8;n++){
            o[n][0]*=a0; o[n][1]*=a0; o[n][2]*=a1; o[n][3]*=a1;
        }

        // P -> warp-private smem slab (C-layout to A-layout shuffle)
        #pragma unroll
        for (int n=0;n<8;n++){
            *(float2*)&Qs[ pr   *ALD + n*8 + 2*tig] = make_float2(s[n][0], s[n][1]);
            *(float2*)&Qs[(pr+8)*ALD + n*8 + 2*tig] = make_float2(s[n][2], s[n][3]);
        }
        __syncwarp();

        // O += P @ V
        #pragma unroll
        for (int kk=0;kk<8;kk++){
            uint32_t pa[4];
            pa[0] = __float_as_uint(Qs[ pr   *ALD + kk*8 + tig    ]);
            pa[1] = __float_as_uint(Qs[(pr+8)*ALD + kk*8 + tig    ]);
            pa[2] = __float_as_uint(Qs[ pr   *ALD + kk*8 + tig + 4]);
            pa[3] = __float_as_uint(Qs[(pr+8)*ALD + kk*8 + tig + 4]);
            #pragma unroll
            for (int n=0;n<8;n++){
                uint32_t b0 = __float_as_uint(Vs[(kk*8+tig  )*ALD + n*8 + g]);
                uint32_t b1 = __float_as_uint(Vs[(kk*8+tig+4)*ALD + n*8 + g]);
                mma8(o[n], pa, b0, b1);
            }
        }
    }

    // normalize and write out (float2, C-layout cols adjacent)
    float inv0 = 1.f/l0, inv1 = 1.f/l1;
    const int r0 = qrow0 + pr;
    #pragma unroll
    for (int n=0;n<8;n++){
        *(float2*)&g_att[(rowBase + r0    )*DD + colBase + n*8 + 2*tig] =
            make_float2(o[n][0]*inv0, o[n][1]*inv0);
        *(float2*)&g_att[(rowBase + r0 + 8)*DD + colBase + n*8 + 2*tig] =
            make_float2(o[n][2]*inv1, o[n][3]*inv1);
    }
}

// ===========================================================================
// LayerNorm over D=512 of (in + bias + resid): one block per row, 128 threads
// ===========================================================================
__global__ __launch_bounds__(128) void ln_kernel(
    const float* __restrict__ in, const float* __restrict__ bias,
    const float* __restrict__ resid,
    const float* __restrict__ gamma, const float* __restrict__ beta,
    float* __restrict__ out)
{
    __shared__ float sh[8];
    const int row = blockIdx.x;
    const size_t base = (size_t)row * DD;
    float v[4];
    #pragma unroll
    for (int j=0;j<4;j++){
        int c = threadIdx.x + j*128;
        v[j] = in[base + c] + bias[c] + resid[base + c];
    }
    float s = v[0]+v[1]+v[2]+v[3];
    #pragma unroll
    for (int o=16;o>0;o>>=1) s += __shfl_xor_sync(0xffffffffu, s, o);
    if ((threadIdx.x & 31)==0) sh[threadIdx.x>>5] = s;
    __syncthreads();
    float mean = (sh[0]+sh[1]+sh[2]+sh[3]) * (1.0f/DD);
    float sq = 0.0f;
    #pragma unroll
    for (int j=0;j<4;j++){ float d = v[j]-mean; sq += d*d; }
    #pragma unroll
    for (int o=16;o>0;o>>=1) sq += __shfl_xor_sync(0xffffffffu, sq, o);
    __syncthreads();
    if ((threadIdx.x & 31)==0) sh[4 + (threadIdx.x>>5)] = sq;
    __syncthreads();
    float var = (sh[4]+sh[5]+sh[6]+sh[7]) * (1.0f/DD);
    float rstd = rsqrtf(var + EPS);
    #pragma unroll
    for (int j=0;j<4;j++){
        int c = threadIdx.x + j*128;
        out[base + c] = (v[j]-mean)*rstd*gamma[c] + beta[c];
    }
}

// ===========================================================================
// bias + relu elementwise on [MTOT, FFD]
// ===========================================================================
__global__ __launch_bounds__(256) void bias_relu_kernel(
    float* __restrict__ hbuf, const float* __restrict__ b1)
{
    const size_t n4 = (size_t)MTOT * FFD / 4;
    for (size_t i = blockIdx.x*blockDim.x + threadIdx.x; i < n4; i += (size_t)gridDim.x*blockDim.x){
        float4 val = *(float4*)&hbuf[i*4];
        int col = (int)((i*4) % FFD);
        val.x = fmaxf(val.x + b1[col+0], 0.0f);
        val.y = fmaxf(val.y + b1[col+1], 0.0f);
        val.z = fmaxf(val.z + b1[col+2], 0.0f);
        val.w = fmaxf(val.w + b1[col+3], 0.0f);
        *(float4*)&hbuf[i*4] = val;
    }
}

// ===========================================================================
extern "C" void kernel_launch(void* const* d_in, const int* in_sizes, int n_in,
                              void* d_out, int out_size)
{
    const float* x     = (const float*)d_in[0];
    const float* WQ    = (const float*)d_in[1];
    const float* WK    = (const float*)d_in[2];
    const float* WV    = (const float*)d_in[3];
    const float* WZ    = (const float*)d_in[4];
    const float* bZ    = (const float*)d_in[5];
    const float* W1    = (const float*)d_in[6];
    const float* b1    = (const float*)d_in[7];
    const float* W2    = (const float*)d_in[8];
    const float* b2    = (const float*)d_in[9];
    const float* gamma = (const float*)d_in[10];
    const float* beta  = (const float*)d_in[11];
    float* out = (float*)d_out;

    float *q, *k, *v, *att, *t1, *zn, *hbuf, *o2;
    cudaGetSymbolAddress((void**)&q,    g_q);
    cudaGetSymbolAddress((void**)&k,    g_k);
    cudaGetSymbolAddress((void**)&v,    g_v);
    cudaGetSymbolAddress((void**)&att,  g_att);
    cudaGetSymbolAddress((void**)&t1,   g_t1);
    cudaGetSymbolAddress((void**)&zn,   g_zn);
    cudaGetSymbolAddress((void**)&hbuf, g_h);
    cudaGetSymbolAddress((void**)&o2,   g_o2);

    cudaFuncSetAttribute(gemm_k,     cudaFuncAttributeMaxDynamicSharedMemorySize, GEMM_SMEM);
    cudaFuncSetAttribute(gemm_qkv_k, cudaFuncAttributeMaxDynamicSharedMemorySize, GEMM_SMEM);
    cudaFuncSetAttribute(attn_kernel,cudaFuncAttributeMaxDynamicSharedMemorySize, ATT_SMEM);

    // QKV projections (batched in one launch via gridDim.z)
    gemm_qkv_k<<<dim3(DD/128, MTOT/128, 3), 256, GEMM_SMEM>>>(x, WQ, WK, WV, q, k, v, MTOT, DD, DD);
    // attention
    attn_kernel<<<dim3(LL/64, BB*HH), 128, ATT_SMEM>>>();
    // z @ WZ
    gemm_k<<<dim3(DD/128, MTOT/128), 256, GEMM_SMEM>>>(att, WZ, t1, MTOT, DD, DD);
    // LN1: LN(t1 + bZ + x)
    ln_kernel<<<MTOT, 128>>>(t1, bZ, x, gamma, beta, zn);
    // FF
    gemm_k<<<dim3(FFD/128, MTOT/128), 256, GEMM_SMEM>>>(zn, W1, hbuf, MTOT, FFD, DD);
    bias_relu_kernel<<<4096, 256>>>(hbuf, b1);
    gemm_k<<<dim3(DD/128, MTOT/128), 256, GEMM_SMEM>>>(hbuf, W2, o2, MTOT, DD, FFD);
    // LN2: LN(o2 + b2 + zn) -> out
    ln_kernel<<<MTOT, 128>>>(o2, b2, zn, gamma, beta, out);
}

// round 5
// speedup vs baseline: 5.2870x; 3.3457x over previous
#include <cuda_runtime.h>
#include <cuda_fp16.h>
#include <math.h>
#include <stdint.h>

// Problem constants
#define BB 4
#define LL 2048
#define DD 512
#define HH 8
#define QDIM 64
#define FFD 2048
#define MTOT (BB*LL)          // 8192
#define EPS 1e-5f
#define ATT_SCALE 0.125f

// -------------------- scratch (device globals) ----------------------------
__device__ float  g_t1 [MTOT*DD];
__device__ float  g_zn [MTOT*DD];
__device__ float  g_o2 [MTOT*DD];
__device__ __half g_xh [MTOT*DD];
__device__ __half g_wqh[DD*DD];
__device__ __half g_wkh[DD*DD];
__device__ __half g_wvh[DD*DD];
__device__ __half g_wzh[DD*DD];
__device__ __half g_w1h[DD*FFD];
__device__ __half g_w2h[FFD*DD];
__device__ __half g_qh [MTOT*DD];
__device__ __half g_kh [MTOT*DD];
__device__ __half g_vh [MTOT*DD];
__device__ __half g_atth[MTOT*DD];
__device__ __half g_znh[MTOT*DD];
__device__ __half g_hh [MTOT*FFD];

// -------------------- PTX helpers -----------------------------------------
__device__ __forceinline__ void cp16h(__half* s, const __half* g) {
    uint32_t sa = (uint32_t)__cvta_generic_to_shared(s);
    asm volatile("cp.async.cg.shared.global [%0], [%1], 16;\n" :: "r"(sa), "l"(g));
}
__device__ __forceinline__ void cp_commit() { asm volatile("cp.async.commit_group;\n"); }
template<int N> __device__ __forceinline__ void cp_wait() {
    asm volatile("cp.async.wait_group %0;\n" :: "n"(N));
}
__device__ __forceinline__ uint32_t s2u(const void* p) {
    return (uint32_t)__cvta_generic_to_shared(p);
}
__device__ __forceinline__ void ldm4(uint32_t addr, uint32_t* r) {
    asm volatile("ldmatrix.sync.aligned.m8n8.x4.shared.b16 {%0,%1,%2,%3}, [%4];\n"
        : "=r"(r[0]), "=r"(r[1]), "=r"(r[2]), "=r"(r[3]) : "r"(addr));
}
__device__ __forceinline__ void ldm4t(uint32_t addr, uint32_t* r) {
    asm volatile("ldmatrix.sync.aligned.m8n8.x4.trans.shared.b16 {%0,%1,%2,%3}, [%4];\n"
        : "=r"(r[0]), "=r"(r[1]), "=r"(r[2]), "=r"(r[3]) : "r"(addr));
}
__device__ __forceinline__ void mma16(float* d, const uint32_t* a, uint32_t b0, uint32_t b1) {
    asm volatile("mma.sync.aligned.m16n8k16.row.col.f32.f16.f16.f32 "
        "{%0,%1,%2,%3}, {%4,%5,%6,%7}, {%8,%9}, {%0,%1,%2,%3};\n"
        : "+f"(d[0]), "+f"(d[1]), "+f"(d[2]), "+f"(d[3])
        : "r"(a[0]), "r"(a[1]), "r"(a[2]), "r"(a[3]), "r"(b0), "r"(b1));
}
__device__ __forceinline__ uint32_t h2u(__half2 h) { return *(uint32_t*)&h; }

// ===========================================================================
// fp16 GEMM: C[M,N] = A[M,K]@B[K,N]. Block 128x128, BK=32, 3-stage cp.async.
// 256 threads, warp tile 64x32, mma.m16n8k16 via ldmatrix.
// EPI: 0 = fp32 store, 1 = fp16 store, 2 = fp16 bias+relu store.
// ===========================================================================
#define GH_ALD 40
#define GH_BLD 136
#define GH_ASZ (128*GH_ALD)
#define GH_BSZ (32*GH_BLD)
#define GH_SMEM (3*(GH_ASZ+GH_BSZ)*2)

template<int EPI>
__device__ __forceinline__ void gemm_h_body(
    const __half* __restrict__ A, const __half* __restrict__ B,
    float* __restrict__ Cf, __half* __restrict__ Ch, const float* __restrict__ bias,
    int M, int N, int K, int mBase, int nBase)
{
    extern __shared__ __half hsm[];
    __half* As = hsm;
    __half* Bs = hsm + 3*GH_ASZ;
    const int tid = threadIdx.x, w = tid >> 5, lane = tid & 31;
    const int wm = w >> 2, wn = w & 3;
    const int g = lane >> 2, tig = lane & 3;

    auto load_stage = [&](int st, int k0) {
        __half* as = As + st*GH_ASZ;
        __half* bs = Bs + st*GH_BSZ;
        #pragma unroll
        for (int i=0;i<2;i++){
            int f = tid + i*256; int r = f>>2, c = f&3;
            cp16h(&as[r*GH_ALD + c*8], &A[(size_t)(mBase+r)*K + k0 + c*8]);
        }
        #pragma unroll
        for (int i=0;i<2;i++){
            int f = tid + i*256; int r = f>>4, c = f&15;
            cp16h(&bs[r*GH_BLD + c*8], &B[(size_t)(k0+r)*N + nBase + c*8]);
        }
        cp_commit();
    };

    float acc[4][4][4];
    #pragma unroll
    for (int mt=0;mt<4;mt++)
        #pragma unroll
        for (int nt=0;nt<4;nt++)
            #pragma unroll
            for (int e=0;e<4;e++) acc[mt][nt][e] = 0.f;

    const int nk = K/32;
    load_stage(0, 0);
    load_stage(1, 32);

    for (int kt=0; kt<nk; kt++){
        cp_wait<1>();
        __syncthreads();
        if (kt+2 < nk) load_stage((kt+2)%3, (kt+2)*32);

        uint32_t ab = s2u(As + (kt%3)*GH_ASZ);
        uint32_t bb = s2u(Bs + (kt%3)*GH_BSZ);
        #pragma unroll
        for (int ks=0; ks<2; ks++){
            uint32_t aw[4][4], bw[2][4];
            #pragma unroll
            for (int mt=0;mt<4;mt++)
                ldm4(ab + ((wm*64 + mt*16 + (lane&15))*GH_ALD + ks*16 + (lane>>4)*8)*2, aw[mt]);
            #pragma unroll
            for (int p=0;p<2;p++)
                ldm4t(bb + ((ks*16 + (lane&7) + ((lane>>3)&1)*8)*GH_BLD + wn*32 + p*16 + (lane>>4)*8)*2, bw[p]);
            #pragma unroll
            for (int mt=0;mt<4;mt++)
                #pragma unroll
                for (int p=0;p<2;p++){
                    mma16(acc[mt][2*p  ], aw[mt], bw[p][0], bw[p][1]);
                    mma16(acc[mt][2*p+1], aw[mt], bw[p][2], bw[p][3]);
                }
        }
    }

    #pragma unroll
    for (int mt=0;mt<4;mt++)
        #pragma unroll
        for (int nt=0;nt<4;nt++){
            float* a = acc[mt][nt];
            int r = mBase + wm*64 + mt*16 + g;
            int c = nBase + wn*32 + nt*8 + 2*tig;
            if (EPI == 0){
                *(float2*)&Cf[(size_t)r*N + c]     = make_float2(a[0], a[1]);
                *(float2*)&Cf[(size_t)(r+8)*N + c] = make_float2(a[2], a[3]);
            } else if (EPI == 1){
                *(__half2*)&Ch[(size_t)r*N + c]     = __floats2half2_rn(a[0], a[1]);
                *(__half2*)&Ch[(size_t)(r+8)*N + c] = __floats2half2_rn(a[2], a[3]);
            } else {
                float2 bv = *(const float2*)&bias[c];
                *(__half2*)&Ch[(size_t)r*N + c] =
                    __floats2half2_rn(fmaxf(a[0]+bv.x,0.f), fmaxf(a[1]+bv.y,0.f));
                *(__half2*)&Ch[(size_t)(r+8)*N + c] =
                    __floats2half2_rn(fmaxf(a[2]+bv.x,0.f), fmaxf(a[3]+bv.y,0.f));
            }
        }
}

template<int EPI>
__global__ __launch_bounds__(256,2) void gemm_h(
    const __half* __restrict__ A, const __half* __restrict__ B,
    float* __restrict__ Cf, __half* __restrict__ Ch, const float* __restrict__ bias,
    int M, int N, int K)
{
    gemm_h_body<EPI>(A, B, Cf, Ch, bias, M, N, K, blockIdx.y*128, blockIdx.x*128);
}

__global__ __launch_bounds__(256,2) void gemm_qkv(
    const __half* __restrict__ A,
    const __half* __restrict__ B0, const __half* __restrict__ B1, const __half* __restrict__ B2,
    __half* __restrict__ C0, __half* __restrict__ C1, __half* __restrict__ C2,
    int M, int N, int K)
{
    const __half* B = (blockIdx.z==0) ? B0 : (blockIdx.z==1 ? B1 : B2);
    __half*       C = (blockIdx.z==0) ? C0 : (blockIdx.z==1 ? C1 : C2);
    gemm_h_body<1>(A, B, nullptr, C, nullptr, M, N, K, blockIdx.y*128, blockIdx.x*128);
}

// ===========================================================================
// FA2-style fp16 flash attention. 128 threads (4 warps), warp = 16 q-rows.
// P stays in registers (acc-frag -> A-frag repack). Double-buffered K/V.
// ===========================================================================
#define ATL 72
#define ATT_TILE (64*ATL)
#define ATT_SMEM (5*ATT_TILE*2)

__global__ __launch_bounds__(128) void attn_h_kernel(
    const __half* __restrict__ qh, const __half* __restrict__ kh,
    const __half* __restrict__ vh, __half* __restrict__ atth)
{
    extern __shared__ __half hsm[];
    __half* Qs  = hsm;
    __half* Ksb[2] = { hsm + ATT_TILE,   hsm + 2*ATT_TILE };
    __half* Vsb[2] = { hsm + 3*ATT_TILE, hsm + 4*ATT_TILE };

    const int tid = threadIdx.x, w = tid >> 5, lane = tid & 31;
    const int g = lane >> 2, tig = lane & 3;
    const int qtile = blockIdx.x, bh = blockIdx.y;
    const int b = bh >> 3, h = bh & 7;
    const size_t rowBase = (size_t)b * LL;
    const int colBase = h * QDIM;
    const int qrow0 = qtile * 64;
    const int NT = LL/64;

    auto loadKV = [&](int buf, int t) {
        #pragma unroll
        for (int i=0;i<4;i++){
            int f = tid + i*128; int r = f>>3, c = f&7;
            cp16h(&Ksb[buf][r*ATL + c*8], &kh[(rowBase + t*64 + r)*DD + colBase + c*8]);
            cp16h(&Vsb[buf][r*ATL + c*8], &vh[(rowBase + t*64 + r)*DD + colBase + c*8]);
        }
        cp_commit();
    };

    // Q tile -> smem
    #pragma unroll
    for (int i=0;i<4;i++){
        int f = tid + i*128; int r = f>>3, c = f&7;
        cp16h(&Qs[r*ATL + c*8], &qh[(rowBase + qrow0 + r)*DD + colBase + c*8]);
    }
    cp_commit();
    loadKV(0, 0);
    cp_wait<0>(); __syncthreads();

    // persistent Q A-fragments
    uint32_t qb = s2u(Qs);
    uint32_t qf[4][4];
    #pragma unroll
    for (int ks=0;ks<4;ks++)
        ldm4(qb + ((w*16 + (lane&15))*ATL + ks*16 + (lane>>4)*8)*2, qf[ks]);

    float o[8][4];
    #pragma unroll
    for (int n=0;n<8;n++){ o[n][0]=o[n][1]=o[n][2]=o[n][3]=0.f; }
    float m0=-1e30f, m1=-1e30f, l0=0.f, l1=0.f;

    for (int kt=0; kt<NT; kt++){
        __syncthreads();
        if (kt+1 < NT){ loadKV((kt+1)&1, kt+1); cp_wait<1>(); }
        else          { cp_wait<0>(); }
        __syncthreads();

        uint32_t kb = s2u(Ksb[kt&1]);
        uint32_t vb = s2u(Vsb[kt&1]);

        // S = Q @ K^T
        // K fragment (non-trans ldmatrix from row-major [key][dim]):
        // FIX vs R4: (lane>>3)&1 selects the DIM half (column), lane>>4 selects
        // the KEY half (row), so r0/r1 = keys0-8 dims{0-8,8-16} (b0,b1 of n-tile0)
        // and r2/r3 = keys8-16 (b0,b1 of n-tile1).
        float s[8][4];
        #pragma unroll
        for (int n=0;n<8;n++){ s[n][0]=s[n][1]=s[n][2]=s[n][3]=0.f; }
        #pragma unroll
        for (int ks=0;ks<4;ks++){
            uint32_t bw[4][4];
            #pragma unroll
            for (int p=0;p<4;p++)
                ldm4(kb + ((p*16 + (lane&7) + (lane>>4)*8)*ATL + ks*16 + ((lane>>3)&1)*8)*2, bw[p]);
            #pragma unroll
            for (int p=0;p<4;p++){
                mma16(s[2*p  ], qf[ks], bw[p][0], bw[p][1]);
                mma16(s[2*p+1], qf[ks], bw[p][2], bw[p][3]);
            }
        }

        // online softmax (rows g / g+8)
        float mx0=-1e30f, mx1=-1e30f;
        #pragma unroll
        for (int n=0;n<8;n++){
            mx0 = fmaxf(mx0, fmaxf(s[n][0], s[n][1]));
            mx1 = fmaxf(mx1, fmaxf(s[n][2], s[n][3]));
        }
        mx0 = fmaxf(mx0, __shfl_xor_sync(0xffffffffu, mx0, 1));
        mx0 = fmaxf(mx0, __shfl_xor_sync(0xffffffffu, mx0, 2));
        mx1 = fmaxf(mx1, __shfl_xor_sync(0xffffffffu, mx1, 1));
        mx1 = fmaxf(mx1, __shfl_xor_sync(0xffffffffu, mx1, 2));
        float nm0 = fmaxf(m0, mx0*ATT_SCALE);
        float nm1 = fmaxf(m1, mx1*ATT_SCALE);
        float a0 = __expf(m0 - nm0), a1 = __expf(m1 - nm1);
        float sum0 = 0.f, sum1 = 0.f;
        #pragma unroll
        for (int n=0;n<8;n++){
            s[n][0] = __expf(s[n][0]*ATT_SCALE - nm0);
            s[n][1] = __expf(s[n][1]*ATT_SCALE - nm0);
            s[n][2] = __expf(s[n][2]*ATT_SCALE - nm1);
            s[n][3] = __expf(s[n][3]*ATT_SCALE - nm1);
            sum0 += s[n][0] + s[n][1];
            sum1 += s[n][2] + s[n][3];
        }
        sum0 += __shfl_xor_sync(0xffffffffu, sum0, 1);
        sum0 += __shfl_xor_sync(0xffffffffu, sum0, 2);
        sum1 += __shfl_xor_sync(0xffffffffu, sum1, 1);
        sum1 += __shfl_xor_sync(0xffffffffu, sum1, 2);
        l0 = l0*a0 + sum0;  l1 = l1*a1 + sum1;
        m0 = nm0;  m1 = nm1;
        #pragma unroll
        for (int n=0;n<8;n++){
            o[n][0]*=a0; o[n][1]*=a0; o[n][2]*=a1; o[n][3]*=a1;
        }

        // O += P @ V  (P repacked from S accumulators, registers only)
        #pragma unroll
        for (int ks=0;ks<4;ks++){
            uint32_t pa[4];
            pa[0] = h2u(__floats2half2_rn(s[2*ks  ][0], s[2*ks  ][1]));
            pa[1] = h2u(__floats2half2_rn(s[2*ks  ][2], s[2*ks  ][3]));
            pa[2] = h2u(__floats2half2_rn(s[2*ks+1][0], s[2*ks+1][1]));
            pa[3] = h2u(__floats2half2_rn(s[2*ks+1][2], s[2*ks+1][3]));
            uint32_t vw[4][4];
            #pragma unroll
            for (int p=0;p<4;p++)
                ldm4t(vb + ((ks*16 + (lane&7) + ((lane>>3)&1)*8)*ATL + p*16 + (lane>>4)*8)*2, vw[p]);
            #pragma unroll
            for (int p=0;p<4;p++){
                mma16(o[2*p  ], pa, vw[p][0], vw[p][1]);
                mma16(o[2*p+1], pa, vw[p][2], vw[p][3]);
            }
        }
    }

    // normalize + store half
    float inv0 = 1.f/l0, inv1 = 1.f/l1;
    const size_t r0 = rowBase + qrow0 + w*16 + g;
    #pragma unroll
    for (int n=0;n<8;n++){
        *(__half2*)&atth[ r0     *DD + colBase + n*8 + 2*tig] =
            __floats2half2_rn(o[n][0]*inv0, o[n][1]*inv0);
        *(__half2*)&atth[(r0 + 8)*DD + colBase + n*8 + 2*tig] =
            __floats2half2_rn(o[n][2]*inv1, o[n][3]*inv1);
    }
}

// ===========================================================================
// LayerNorm over D=512 of (in + bias + resid); optional fp16 copy out.
// ===========================================================================
__global__ __launch_bounds__(128) void ln_kernel(
    const float* __restrict__ in, const float* __restrict__ bias,
    const float* __restrict__ resid,
    const float* __restrict__ gamma, const float* __restrict__ beta,
    float* __restrict__ out, __half* __restrict__ out_h)
{
    __shared__ float sh[8];
    const int row = blockIdx.x;
    const size_t base = (size_t)row * DD;
    float v[4];
    #pragma unroll
    for (int j=0;j<4;j++){
        int c = threadIdx.x + j*128;
        v[j] = in[base + c] + bias[c] + resid[base + c];
    }
    float s = v[0]+v[1]+v[2]+v[3];
    #pragma unroll
    for (int o=16;o>0;o>>=1) s += __shfl_xor_sync(0xffffffffu, s, o);
    if ((threadIdx.x & 31)==0) sh[threadIdx.x>>5] = s;
    __syncthreads();
    float mean = (sh[0]+sh[1]+sh[2]+sh[3]) * (1.0f/DD);
    float sq = 0.0f;
    #pragma unroll
    for (int j=0;j<4;j++){ float d = v[j]-mean; sq += d*d; }
    #pragma unroll
    for (int o=16;o>0;o>>=1) sq += __shfl_xor_sync(0xffffffffu, sq, o);
    __syncthreads();
    if ((threadIdx.x & 31)==0) sh[4 + (threadIdx.x>>5)] = sq;
    __syncthreads();
    float var = (sh[4]+sh[5]+sh[6]+sh[7]) * (1.0f/DD);
    float rstd = rsqrtf(var + EPS);
    #pragma unroll
    for (int j=0;j<4;j++){
        int c = threadIdx.x + j*128;
        float r = (v[j]-mean)*rstd*gamma[c] + beta[c];
        out[base + c] = r;
        if (out_h) out_h[base + c] = __float2half_rn(r);
    }
}

// ===========================================================================
// fp32 -> fp16 convert: 7 tensors in one launch via blockIdx.y
// ===========================================================================
__global__ __launch_bounds__(256) void f2h7(
    const float* i0, __half* o0, int n0, const float* i1, __half* o1, int n1,
    const float* i2, __half* o2, int n2, const float* i3, __half* o3, int n3,
    const float* i4, __half* o4, int n4_, const float* i5, __half* o5, int n5,
    const float* i6, __half* o6, int n6)
{
    const float* in; __half* out; int n;
    switch (blockIdx.y){
        case 0: in=i0; out=o0; n=n0; break;
        case 1: in=i1; out=o1; n=n1; break;
        case 2: in=i2; out=o2; n=n2; break;
        case 3: in=i3; out=o3; n=n3; break;
        case 4: in=i4; out=o4; n=n4_; break;
        case 5: in=i5; out=o5; n=n5; break;
        default: in=i6; out=o6; n=n6; break;
    }
    int idx = blockIdx.x*256 + threadIdx.x;
    int q = n >> 2;
    if (idx < q){
        float4 v = ((const float4*)in)[idx];
        ((__half2*)out)[idx*2  ] = __floats2half2_rn(v.x, v.y);
        ((__half2*)out)[idx*2+1] = __floats2half2_rn(v.z, v.w);
    }
}

// ===========================================================================
extern "C" void kernel_launch(void* const* d_in, const int* in_sizes, int n_in,
                              void* d_out, int out_size)
{
    const float* x     = (const float*)d_in[0];
    const float* WQ    = (const float*)d_in[1];
    const float* WK    = (const float*)d_in[2];
    const float* WV    = (const float*)d_in[3];
    const float* WZ    = (const float*)d_in[4];
    const float* bZ    = (const float*)d_in[5];
    const float* W1    = (const float*)d_in[6];
    const float* b1    = (const float*)d_in[7];
    const float* W2    = (const float*)d_in[8];
    const float* b2    = (const float*)d_in[9];
    const float* gamma = (const float*)d_in[10];
    const float* beta  = (const float*)d_in[11];
    float* out = (float*)d_out;

    float  *t1, *zn, *o2;
    __half *xh,*wqh,*wkh,*wvh,*wzh,*w1h,*w2h,*qh,*kh,*vh,*atth,*znh,*hh;
    cudaGetSymbolAddress((void**)&t1,  g_t1);
    cudaGetSymbolAddress((void**)&zn,  g_zn);
    cudaGetSymbolAddress((void**)&o2,  g_o2);
    cudaGetSymbolAddress((void**)&xh,  g_xh);
    cudaGetSymbolAddress((void**)&wqh, g_wqh);
    cudaGetSymbolAddress((void**)&wkh, g_wkh);
    cudaGetSymbolAddress((void**)&wvh, g_wvh);
    cudaGetSymbolAddress((void**)&wzh, g_wzh);
    cudaGetSymbolAddress((void**)&w1h, g_w1h);
    cudaGetSymbolAddress((void**)&w2h, g_w2h);
    cudaGetSymbolAddress((void**)&qh,  g_qh);
    cudaGetSymbolAddress((void**)&kh,  g_kh);
    cudaGetSymbolAddress((void**)&vh,  g_vh);
    cudaGetSymbolAddress((void**)&atth,g_atth);
    cudaGetSymbolAddress((void**)&znh, g_znh);
    cudaGetSymbolAddress((void**)&hh,  g_hh);

    cudaFuncSetAttribute(gemm_h<0>,   cudaFuncAttributeMaxDynamicSharedMemorySize, GH_SMEM);
    cudaFuncSetAttribute(gemm_h<2>,   cudaFuncAttributeMaxDynamicSharedMemorySize, GH_SMEM);
    cudaFuncSetAttribute(gemm_qkv,    cudaFuncAttributeMaxDynamicSharedMemorySize, GH_SMEM);
    cudaFuncSetAttribute(attn_h_kernel, cudaFuncAttributeMaxDynamicSharedMemorySize, ATT_SMEM);

    // convert inputs + weights to fp16 (RN)
    f2h7<<<dim3(4096,7), 256>>>(
        x,  xh,  MTOT*DD,
        WQ, wqh, DD*DD,  WK, wkh, DD*DD,  WV, wvh, DD*DD,  WZ, wzh, DD*DD,
        W1, w1h, DD*FFD, W2, w2h, FFD*DD);

    // QKV projections -> fp16 q/k/v
    gemm_qkv<<<dim3(DD/128, MTOT/128, 3), 256, GH_SMEM>>>(
        xh, wqh, wkh, wvh, qh, kh, vh, MTOT, DD, DD);

    // flash attention -> fp16 att
    attn_h_kernel<<<dim3(LL/64, BB*HH), 128, ATT_SMEM>>>(qh, kh, vh, atth);

    // att @ WZ -> fp32 t1
    gemm_h<0><<<dim3(DD/128, MTOT/128), 256, GH_SMEM>>>(
        atth, wzh, t1, nullptr, nullptr, MTOT, DD, DD);

    // LN1: LN(t1 + bZ + x) -> zn (fp32) + znh (fp16)
    ln_kernel<<<MTOT, 128>>>(t1, bZ, x, gamma, beta, zn, znh);

    // FF1: zn @ W1 + b1, relu -> fp16 hh
    gemm_h<2><<<dim3(FFD/128, MTOT/128), 256, GH_SMEM>>>(
        znh, w1h, nullptr, hh, b1, MTOT, FFD, DD);

    // FF2: hh @ W2 -> fp32 o2
    gemm_h<0><<<dim3(DD/128, MTOT/128), 256, GH_SMEM>>>(
        hh, w2h, o2, nullptr, nullptr, MTOT, DD, FFD);

    // LN2: LN(o2 + b2 + zn) -> out
    ln_kernel<<<MTOT, 128>>>(o2, b2, zn, gamma, beta, out, nullptr);
}